// round 7
// baseline (speedup 1.0000x reference)
#include <cuda_runtime.h>
#include <cuda_bf16.h>
#include <math.h>

#define D_MODEL 1024
#define D_KEY   128
#define N_SUB   256
#define TOPK    8
#define MAXNT   8192

// -------- scratch (device globals) --------
__device__ __align__(128) __nv_bfloat16 g_xb [MAXNT * D_MODEL];
__device__ __align__(128) __nv_bfloat16 g_wqb[2 * D_KEY * D_MODEL];
__device__ __align__(128) __nv_bfloat16 g_kb [2 * N_SUB * D_KEY];
__device__ __align__(128) __nv_bfloat16 g_qb [MAXNT * 2 * D_KEY];
__device__ __align__(128) float g_scores[MAXNT * 2 * N_SUB];

// ================= base-PTX helpers =================
__device__ __forceinline__ unsigned smem_u32(const void* p) {
    unsigned a;
    asm("{ .reg .u64 t; cvta.to.shared.u64 t, %1; cvt.u32.u64 %0, t; }" : "=r"(a) : "l"(p));
    return a;
}
__device__ __forceinline__ void cpa16(unsigned d, const void* s) {
    asm volatile("cp.async.cg.shared.global [%0], [%1], 16;" :: "r"(d), "l"(s));
}
__device__ __forceinline__ void cpcommit() { asm volatile("cp.async.commit_group;" ::: "memory"); }
template<int N> __device__ __forceinline__ void cpwait() {
    asm volatile("cp.async.wait_group %0;" :: "n"(N) : "memory");
}
__device__ __forceinline__ void ldsm4(unsigned addr, unsigned& r0, unsigned& r1,
                                      unsigned& r2, unsigned& r3) {
    asm volatile("ldmatrix.sync.aligned.m8n8.x4.shared.b16 {%0,%1,%2,%3}, [%4];"
                 : "=r"(r0), "=r"(r1), "=r"(r2), "=r"(r3) : "r"(addr));
}
__device__ __forceinline__ void mma16816(float* c, const unsigned* a, const unsigned* b) {
    asm volatile("mma.sync.aligned.m16n8k16.row.col.f32.bf16.bf16.f32 "
                 "{%0,%1,%2,%3}, {%4,%5,%6,%7}, {%8,%9}, {%0,%1,%2,%3};"
                 : "+f"(c[0]), "+f"(c[1]), "+f"(c[2]), "+f"(c[3])
                 : "r"(a[0]), "r"(a[1]), "r"(a[2]), "r"(a[3]), "r"(b[0]), "r"(b[1]));
}
__device__ __forceinline__ unsigned pk_bf16x2(float a, float b) {
    __nv_bfloat162 h = __floats2bfloat162_rn(a, b);
    return *(unsigned*)&h;
}
__device__ __forceinline__ unsigned fmono(float f) {
    unsigned u = __float_as_uint(f);
    return u ^ (((unsigned)((int)u >> 31)) | 0x80000000u);
}
__device__ __forceinline__ float funmono(unsigned m) {
    unsigned u = (m & 0x80000000u) ? (m ^ 0x80000000u) : ~m;
    return __uint_as_float(u);
}
__device__ __forceinline__ unsigned redux_max(unsigned v) {
    unsigned d;
    asm volatile("redux.sync.max.u32 %0, %1, 0xffffffff;" : "=r"(d) : "r"(v));
    return d;
}

// ================= convert fp32 -> bf16 (x, Wq, keys) =================
__global__ __launch_bounds__(256) void convert_kernel(
    const float4* __restrict__ x, const float4* __restrict__ wq,
    const float4* __restrict__ ka, const float4* __restrict__ kb,
    uint2* __restrict__ xb, uint2* __restrict__ wqb, uint2* __restrict__ kbb,
    int X4)
{
    const int W4 = (2 * D_KEY * D_MODEL) / 4;
    const int K4 = (N_SUB * D_KEY) / 4;
    int i = blockIdx.x * blockDim.x + threadIdx.x;
    float4 v; uint2 o;
    if (i < X4) {
        v = x[i];
        o.x = pk_bf16x2(v.x, v.y); o.y = pk_bf16x2(v.z, v.w);
        xb[i] = o;
    } else if (i < X4 + W4) {
        int j = i - X4; v = wq[j];
        o.x = pk_bf16x2(v.x, v.y); o.y = pk_bf16x2(v.z, v.w);
        wqb[j] = o;
    } else if (i < X4 + W4 + K4) {
        int j = i - X4 - W4; v = ka[j];
        o.x = pk_bf16x2(v.x, v.y); o.y = pk_bf16x2(v.z, v.w);
        kbb[j] = o;
    } else if (i < X4 + W4 + 2 * K4) {
        int j = i - X4 - W4 - K4; v = kb[j];
        o.x = pk_bf16x2(v.x, v.y); o.y = pk_bf16x2(v.z, v.w);
        kbb[K4 + j] = o;
    }
}

// ================= HMMA GEMM (as R4/R5/R6) =================
template<bool OUTBF16>
__global__ __launch_bounds__(256) void hmma_gemm(
    const __nv_bfloat16* __restrict__ A, int lda, int aoff_step,
    const __nv_bfloat16* __restrict__ B0, const __nv_bfloat16* __restrict__ B1, int ldb,
    void* __restrict__ Cv, int ldc, int coff_step, int K)
{
    __shared__ __align__(128) char smem[3 * 16384];
    const unsigned sbase = smem_u32(smem);

    const int tid = threadIdx.x, lane = tid & 31, wid = tid >> 5;
    const int m0 = blockIdx.x * 128;
    const int n0 = blockIdx.y * 128;
    const int z  = blockIdx.z;
    const int aoff = z * aoff_step;
    const int coff = z * coff_step;

    const __nv_bfloat16* __restrict__ Ab = A + (size_t)m0 * lda + aoff;
    const __nv_bfloat16* __restrict__ Bb = (z ? B1 : B0) + (size_t)n0 * ldb;

    const int wm = (wid & 1) * 64;
    const int wn = (wid >> 1) * 32;

    const int rowA = wm + (lane & 15);
    const unsigned swzA = ((unsigned)rowA >> 1) & 3;
    const unsigned aBase = (unsigned)rowA * 64;
    const unsigned aSel = lane >> 4;
    const int rowB = wn + (lane & 7) + ((lane >> 4) << 3);
    const unsigned swzB = ((unsigned)rowB >> 1) & 3;
    const unsigned bBase = (unsigned)rowB * 64;
    const unsigned bSel = (lane >> 3) & 1;

    float acc[4][4][4];
    #pragma unroll
    for (int mt = 0; mt < 4; mt++)
        #pragma unroll
        for (int nt = 0; nt < 4; nt++)
            #pragma unroll
            for (int e = 0; e < 4; e++) acc[mt][nt][e] = 0.f;

    const int KT = K >> 5;

    auto fill = [&](int kt, int st) {
        const unsigned base = sbase + st * 16384u;
        const int kb = kt * 32;
        #pragma unroll
        for (int u = 0; u < 2; u++) {
            int idx = tid + u * 256;
            int r = idx >> 2, c = idx & 3;
            unsigned soff = (unsigned)r * 64 + (((unsigned)c ^ (((unsigned)r >> 1) & 3)) << 4);
            cpa16(base + soff,         Ab + (size_t)r * lda + kb + c * 8);
            cpa16(base + 8192u + soff, Bb + (size_t)r * ldb + kb + c * 8);
        }
    };

    fill(0, 0); cpcommit();
    if (KT > 1) fill(1, 1);
    cpcommit();

    for (int kt = 0; kt < KT; kt++) {
        cpwait<1>();
        __syncthreads();
        int pf = kt + 2;
        if (pf < KT) fill(pf, pf % 3);
        cpcommit();

        const unsigned As = sbase + (kt % 3) * 16384u;
        const unsigned Bs = As + 8192u;
        #pragma unroll
        for (int kk = 0; kk < 2; kk++) {
            unsigned a[4][4];
            #pragma unroll
            for (int mt = 0; mt < 4; mt++)
                ldsm4(As + aBase + mt * 1024u + ((((unsigned)(kk * 2) + aSel) ^ swzA) << 4),
                      a[mt][0], a[mt][1], a[mt][2], a[mt][3]);
            unsigned b[4][2];
            #pragma unroll
            for (int g = 0; g < 2; g++) {
                unsigned r0, r1, r2, r3;
                ldsm4(Bs + bBase + g * 1024u + ((((unsigned)(kk * 2) + bSel) ^ swzB) << 4),
                      r0, r1, r2, r3);
                b[g * 2][0] = r0; b[g * 2][1] = r1;
                b[g * 2 + 1][0] = r2; b[g * 2 + 1][1] = r3;
            }
            #pragma unroll
            for (int mt = 0; mt < 4; mt++)
                #pragma unroll
                for (int nt = 0; nt < 4; nt++)
                    mma16816(acc[mt][nt], a[mt], b[nt]);
        }
        __syncthreads();
    }

    const int gid = lane >> 2;
    const int tg  = (lane & 3) * 2;
    if (OUTBF16) {
        __nv_bfloat16* C = (__nv_bfloat16*)Cv;
        #pragma unroll
        for (int mt = 0; mt < 4; mt++) {
            int r = m0 + wm + mt * 16 + gid;
            #pragma unroll
            for (int nt = 0; nt < 4; nt++) {
                int col = coff + n0 + wn + nt * 8 + tg;
                *(unsigned*)(C + (size_t)r * ldc + col)       = pk_bf16x2(acc[mt][nt][0], acc[mt][nt][1]);
                *(unsigned*)(C + (size_t)(r + 8) * ldc + col) = pk_bf16x2(acc[mt][nt][2], acc[mt][nt][3]);
            }
        }
    } else {
        float* C = (float*)Cv;
        #pragma unroll
        for (int mt = 0; mt < 4; mt++) {
            int r = m0 + wm + mt * 16 + gid;
            #pragma unroll
            for (int nt = 0; nt < 4; nt++) {
                int col = coff + n0 + wn + nt * 8 + tg;
                *(float2*)(C + (size_t)r * ldc + col)       = make_float2(acc[mt][nt][0], acc[mt][nt][1]);
                *(float2*)(C + (size_t)(r + 8) * ldc + col) = make_float2(acc[mt][nt][2], acc[mt][nt][3]);
            }
        }
    }
}

// ================= fused topk + softmax + gate + gather + residual =================
// One 256-thread block per token. Warp 0 runs packed-key/redux topk while all
// warps contribute the gate dot-product; then all warps gather values.
__global__ __launch_bounds__(256) void topk_gather(
    const float* __restrict__ scores,
    const float* __restrict__ x, const float* __restrict__ values,
    const float* __restrict__ gate_w, const float* __restrict__ gate_b,
    float* __restrict__ out)
{
    const unsigned FULL = 0xffffffffu;
    const int t = blockIdx.x;
    const int tid = threadIdx.x;
    const int lane = tid & 31, wid = tid >> 5;

    __shared__ float red[8];
    __shared__ float sw[TOPK];
    __shared__ int   sid[TOPK];

    // ---- all warps: gate partial dot product ----
    const float4* xr = (const float4*)(x + (size_t)t * D_MODEL);
    float4 xv = xr[tid];
    float4 gv = ((const float4*)gate_w)[tid];
    float p = xv.x * gv.x + xv.y * gv.y + xv.z * gv.z + xv.w * gv.w;
    #pragma unroll
    for (int off = 16; off; off >>= 1) p += __shfl_down_sync(FULL, p, off);
    if (lane == 0) red[wid] = p;

    // ---- warp 0: top-k ----
    if (wid == 0) {
        const float* row = scores + (size_t)t * (2 * N_SUB);
        unsigned ka[8], kb[8];
        {
            float4 p0 = *(const float4*)(row + lane * 8);
            float4 p1 = *(const float4*)(row + lane * 8 + 4);
            float4 q0 = *(const float4*)(row + 256 + lane * 8);
            float4 q1 = *(const float4*)(row + 256 + lane * 8 + 4);
            float fa[8] = {p0.x, p0.y, p0.z, p0.w, p1.x, p1.y, p1.z, p1.w};
            float fb[8] = {q0.x, q0.y, q0.z, q0.w, q1.x, q1.y, q1.z, q1.w};
            #pragma unroll
            for (int s = 0; s < 8; s++) {
                unsigned tag = 255u - (unsigned)(lane * 8 + s);
                ka[s] = (fmono(fa[s]) & 0xFFFFFF00u) | tag;
                kb[s] = (fmono(fb[s]) & 0xFFFFFF00u) | tag;
            }
        }

        unsigned myA = 0u, myB = 0u;
        #pragma unroll
        for (int it = 0; it < TOPK; it++) {
            unsigned la = ka[0], lb = kb[0];
            #pragma unroll
            for (int s = 1; s < 8; s++) { la = max(la, ka[s]); lb = max(lb, kb[s]); }
            unsigned wa = redux_max(la);
            unsigned wb = redux_max(lb);
            if (lane == it) { myA = wa; myB = wb; }
            #pragma unroll
            for (int s = 0; s < 8; s++) {
                if (ka[s] == wa) ka[s] = 0u;
                if (kb[s] == wb) kb[s] = 0u;
            }
        }

        unsigned a0k = __shfl_sync(FULL, myA, lane >> 3);
        unsigned a1k = __shfl_sync(FULL, myA, (lane >> 3) + 4);
        unsigned bk  = __shfl_sync(FULL, myB, lane & 7);
        float bvf = funmono(bk & 0xFFFFFF00u);
        float c0 = funmono(a0k & 0xFFFFFF00u) + bvf;
        float c1 = funmono(a1k & 0xFFFFFF00u) + bvf;
        int ib  = 255 - (int)(bk & 255u);
        int idx0 = (255 - (int)(a0k & 255u)) * N_SUB + ib;
        int idx1 = (255 - (int)(a1k & 255u)) * N_SUB + ib;
        unsigned k0 = (fmono(c0) & ~63u) | (63u - (unsigned)lane);
        unsigned k1 = (fmono(c1) & ~63u) | (63u - (unsigned)(lane + 32));

        unsigned fkey = 0u; int fid = 0;
        #pragma unroll
        for (int it = 0; it < TOPK; it++) {
            unsigned loc = redux_max(max(k0, k1));
            unsigned pos = 63u - (loc & 63u);
            int src = (int)(pos & 31u);
            int widx = (pos < 32u) ? __shfl_sync(FULL, idx0, src)
                                   : __shfl_sync(FULL, idx1, src);
            if (lane == it) { fkey = loc; fid = widx; }
            if (k0 == loc) k0 = 0u;
            if (k1 == loc) k1 = 0u;
        }

        float val = funmono(fkey & ~63u);
        float v0 = __shfl_sync(FULL, val, 0);
        float e = (lane < TOPK) ? expf(val - v0) : 0.f;
        float ssum = e;
        #pragma unroll
        for (int off = 4; off; off >>= 1) ssum += __shfl_xor_sync(FULL, ssum, off);
        if (lane < TOPK) {
            sw[lane]  = e / ssum;
            sid[lane] = fid;
        }
    }
    __syncthreads();

    // ---- gate value (each thread sums the 8 warp partials) ----
    float s = red[0] + red[1] + red[2] + red[3] + red[4] + red[5] + red[6] + red[7];
    const float g = 1.f / (1.f + expf(-(s + gate_b[0])));

    // ---- gather + weighted sum + residual ----
    float4 acc = make_float4(0.f, 0.f, 0.f, 0.f);
    #pragma unroll
    for (int k = 0; k < TOPK; k++) {
        const float4* vr = (const float4*)(values + (size_t)sid[k] * D_MODEL);
        float4 vv = __ldg(vr + tid);
        float w = sw[k];
        acc.x += w * vv.x; acc.y += w * vv.y; acc.z += w * vv.z; acc.w += w * vv.w;
    }
    float4 o;
    o.x = xv.x + g * acc.x;
    o.y = xv.y + g * acc.y;
    o.z = xv.z + g * acc.z;
    o.w = xv.w + g * acc.w;
    ((float4*)(out + (size_t)t * D_MODEL))[tid] = o;
}

// ================= launch =================
extern "C" void kernel_launch(void* const* d_in, const int* in_sizes, int n_in,
                              void* d_out, int out_size)
{
    const float* x      = (const float*)d_in[0];
    const float* keys_a = (const float*)d_in[1];
    const float* keys_b = (const float*)d_in[2];
    const float* values = (const float*)d_in[3];
    const float* Wq     = (const float*)d_in[4];
    const float* gate_w = (const float*)d_in[5];
    const float* gate_b = (const float*)d_in[6];
    float* out = (float*)d_out;

    const int NT = in_sizes[0] / D_MODEL;   // 8192

    __nv_bfloat16 *xb, *wqb, *kbb, *qb;
    float *sbuf;
    cudaGetSymbolAddress((void**)&xb,   g_xb);
    cudaGetSymbolAddress((void**)&wqb,  g_wqb);
    cudaGetSymbolAddress((void**)&kbb,  g_kb);
    cudaGetSymbolAddress((void**)&qb,   g_qb);
    cudaGetSymbolAddress((void**)&sbuf, g_scores);

    // 0) convert inputs to bf16
    {
        int X4 = NT * D_MODEL / 4;
        int total = X4 + (2 * D_KEY * D_MODEL) / 4 + 2 * (N_SUB * D_KEY) / 4;
        convert_kernel<<<(total + 255) / 256, 256>>>(
            (const float4*)x, (const float4*)Wq, (const float4*)keys_a, (const float4*)keys_b,
            (uint2*)xb, (uint2*)wqb, (uint2*)kbb, X4);
    }
    // 1) q = x @ Wq^T -> bf16 [NT,256]
    {
        dim3 grid(NT / 128, (2 * D_KEY) / 128, 1);
        hmma_gemm<true><<<grid, 256>>>(xb, D_MODEL, 0, wqb, wqb, D_MODEL,
                                       qb, 2 * D_KEY, 0, D_MODEL);
    }
    // 2) scores = q @ keys^T (both halves via grid.z) -> fp32 [NT,512]
    {
        dim3 grid(NT / 128, N_SUB / 128, 2);
        hmma_gemm<false><<<grid, 256>>>(qb, 2 * D_KEY, D_KEY,
                                        kbb, kbb + N_SUB * D_KEY, D_KEY,
                                        sbuf, 2 * N_SUB, N_SUB, D_KEY);
    }
    // 3) fused topk + gather + gate + residual
    topk_gather<<<NT, 256>>>(sbuf, x, values, gate_w, gate_b, out);
}

// round 8
// speedup vs baseline: 1.0186x; 1.0186x over previous
#include <cuda_runtime.h>
#include <cuda_bf16.h>
#include <math.h>

#define D_MODEL 1024
#define D_KEY   128
#define N_SUB   256
#define TOPK    8
#define MAXNT   8192

// -------- scratch (device globals) --------
__device__ __align__(128) __nv_bfloat16 g_xb [MAXNT * D_MODEL];
__device__ __align__(128) __nv_bfloat16 g_wqb[2 * D_KEY * D_MODEL];
__device__ __align__(128) __nv_bfloat16 g_kb [2 * N_SUB * D_KEY];
__device__ __align__(128) __nv_bfloat16 g_qb [MAXNT * 2 * D_KEY];
__device__ __align__(128) unsigned g_cand[MAXNT * 16];   // 8 packed keys per half
__device__ float g_wts[MAXNT * TOPK];
__device__ int   g_idx[MAXNT * TOPK];

// ================= base-PTX helpers =================
__device__ __forceinline__ unsigned smem_u32(const void* p) {
    unsigned a;
    asm("{ .reg .u64 t; cvta.to.shared.u64 t, %1; cvt.u32.u64 %0, t; }" : "=r"(a) : "l"(p));
    return a;
}
__device__ __forceinline__ void cpa16(unsigned d, const void* s) {
    asm volatile("cp.async.cg.shared.global [%0], [%1], 16;" :: "r"(d), "l"(s));
}
__device__ __forceinline__ void cpcommit() { asm volatile("cp.async.commit_group;" ::: "memory"); }
template<int N> __device__ __forceinline__ void cpwait() {
    asm volatile("cp.async.wait_group %0;" :: "n"(N) : "memory");
}
__device__ __forceinline__ void ldsm4(unsigned addr, unsigned& r0, unsigned& r1,
                                      unsigned& r2, unsigned& r3) {
    asm volatile("ldmatrix.sync.aligned.m8n8.x4.shared.b16 {%0,%1,%2,%3}, [%4];"
                 : "=r"(r0), "=r"(r1), "=r"(r2), "=r"(r3) : "r"(addr));
}
__device__ __forceinline__ void mma16816(float* c, const unsigned* a, const unsigned* b) {
    asm volatile("mma.sync.aligned.m16n8k16.row.col.f32.bf16.bf16.f32 "
                 "{%0,%1,%2,%3}, {%4,%5,%6,%7}, {%8,%9}, {%0,%1,%2,%3};"
                 : "+f"(c[0]), "+f"(c[1]), "+f"(c[2]), "+f"(c[3])
                 : "r"(a[0]), "r"(a[1]), "r"(a[2]), "r"(a[3]), "r"(b[0]), "r"(b[1]));
}
__device__ __forceinline__ unsigned pk_bf16x2(float a, float b) {
    __nv_bfloat162 h = __floats2bfloat162_rn(a, b);
    return *(unsigned*)&h;
}
__device__ __forceinline__ unsigned fmono(float f) {
    unsigned u = __float_as_uint(f);
    return u ^ (((unsigned)((int)u >> 31)) | 0x80000000u);
}
__device__ __forceinline__ float funmono(unsigned m) {
    unsigned u = (m & 0x80000000u) ? (m ^ 0x80000000u) : ~m;
    return __uint_as_float(u);
}
__device__ __forceinline__ unsigned redux_max(unsigned v) {
    unsigned d;
    asm volatile("redux.sync.max.u32 %0, %1, 0xffffffff;" : "=r"(d) : "r"(v));
    return d;
}

// ================= convert fp32 -> bf16 (x, Wq, keys) =================
__global__ __launch_bounds__(256) void convert_kernel(
    const float4* __restrict__ x, const float4* __restrict__ wq,
    const float4* __restrict__ ka, const float4* __restrict__ kb,
    uint2* __restrict__ xb, uint2* __restrict__ wqb, uint2* __restrict__ kbb,
    int X4)
{
    const int W4 = (2 * D_KEY * D_MODEL) / 4;
    const int K4 = (N_SUB * D_KEY) / 4;
    int i = blockIdx.x * blockDim.x + threadIdx.x;
    float4 v; uint2 o;
    if (i < X4) {
        v = x[i];
        o.x = pk_bf16x2(v.x, v.y); o.y = pk_bf16x2(v.z, v.w);
        xb[i] = o;
    } else if (i < X4 + W4) {
        int j = i - X4; v = wq[j];
        o.x = pk_bf16x2(v.x, v.y); o.y = pk_bf16x2(v.z, v.w);
        wqb[j] = o;
    } else if (i < X4 + W4 + K4) {
        int j = i - X4 - W4; v = ka[j];
        o.x = pk_bf16x2(v.x, v.y); o.y = pk_bf16x2(v.z, v.w);
        kbb[j] = o;
    } else if (i < X4 + W4 + 2 * K4) {
        int j = i - X4 - W4 - K4; v = kb[j];
        o.x = pk_bf16x2(v.x, v.y); o.y = pk_bf16x2(v.z, v.w);
        kbb[K4 + j] = o;
    }
}

// ================= GEMM1 (as R4-R6): q = x @ Wq^T -> bf16 =================
__global__ __launch_bounds__(256) void hmma_gemm1(
    const __nv_bfloat16* __restrict__ A, int lda,
    const __nv_bfloat16* __restrict__ B, int ldb,
    __nv_bfloat16* __restrict__ C, int ldc, int K)
{
    __shared__ __align__(128) char smem[3 * 16384];
    const unsigned sbase = smem_u32(smem);

    const int tid = threadIdx.x, lane = tid & 31, wid = tid >> 5;
    const int m0 = blockIdx.x * 128;
    const int n0 = blockIdx.y * 128;

    const __nv_bfloat16* __restrict__ Ab = A + (size_t)m0 * lda;
    const __nv_bfloat16* __restrict__ Bb = B + (size_t)n0 * ldb;

    const int wm = (wid & 1) * 64;
    const int wn = (wid >> 1) * 32;

    const int rowA = wm + (lane & 15);
    const unsigned swzA = ((unsigned)rowA >> 1) & 3;
    const unsigned aBase = (unsigned)rowA * 64;
    const unsigned aSel = lane >> 4;
    const int rowB = wn + (lane & 7) + ((lane >> 4) << 3);
    const unsigned swzB = ((unsigned)rowB >> 1) & 3;
    const unsigned bBase = (unsigned)rowB * 64;
    const unsigned bSel = (lane >> 3) & 1;

    float acc[4][4][4];
    #pragma unroll
    for (int mt = 0; mt < 4; mt++)
        #pragma unroll
        for (int nt = 0; nt < 4; nt++)
            #pragma unroll
            for (int e = 0; e < 4; e++) acc[mt][nt][e] = 0.f;

    const int KT = K >> 5;

    auto fill = [&](int kt, int st) {
        const unsigned base = sbase + st * 16384u;
        const int kb = kt * 32;
        #pragma unroll
        for (int u = 0; u < 2; u++) {
            int idx = tid + u * 256;
            int r = idx >> 2, c = idx & 3;
            unsigned soff = (unsigned)r * 64 + (((unsigned)c ^ (((unsigned)r >> 1) & 3)) << 4);
            cpa16(base + soff,         Ab + (size_t)r * lda + kb + c * 8);
            cpa16(base + 8192u + soff, Bb + (size_t)r * ldb + kb + c * 8);
        }
    };

    fill(0, 0); cpcommit();
    if (KT > 1) fill(1, 1);
    cpcommit();

    for (int kt = 0; kt < KT; kt++) {
        cpwait<1>();
        __syncthreads();
        int pf = kt + 2;
        if (pf < KT) fill(pf, pf % 3);
        cpcommit();

        const unsigned As = sbase + (kt % 3) * 16384u;
        const unsigned Bs = As + 8192u;
        #pragma unroll
        for (int kk = 0; kk < 2; kk++) {
            unsigned a[4][4];
            #pragma unroll
            for (int mt = 0; mt < 4; mt++)
                ldsm4(As + aBase + mt * 1024u + ((((unsigned)(kk * 2) + aSel) ^ swzA) << 4),
                      a[mt][0], a[mt][1], a[mt][2], a[mt][3]);
            unsigned b[4][2];
            #pragma unroll
            for (int g = 0; g < 2; g++) {
                unsigned r0, r1, r2, r3;
                ldsm4(Bs + bBase + g * 1024u + ((((unsigned)(kk * 2) + bSel) ^ swzB) << 4),
                      r0, r1, r2, r3);
                b[g * 2][0] = r0; b[g * 2][1] = r1;
                b[g * 2 + 1][0] = r2; b[g * 2 + 1][1] = r3;
            }
            #pragma unroll
            for (int mt = 0; mt < 4; mt++)
                #pragma unroll
                for (int nt = 0; nt < 4; nt++)
                    mma16816(acc[mt][nt], a[mt], b[nt]);
        }
        __syncthreads();
    }

    const int gid = lane >> 2;
    const int tg  = (lane & 3) * 2;
    #pragma unroll
    for (int mt = 0; mt < 4; mt++) {
        int r = m0 + wm + mt * 16 + gid;
        #pragma unroll
        for (int nt = 0; nt < 4; nt++) {
            int col = n0 + wn + nt * 8 + tg;
            *(unsigned*)(C + (size_t)r * ldc + col)       = pk_bf16x2(acc[mt][nt][0], acc[mt][nt][1]);
            *(unsigned*)(C + (size_t)(r + 8) * ldc + col) = pk_bf16x2(acc[mt][nt][2], acc[mt][nt][3]);
        }
    }
}

// ================= GEMM2 + per-half top-8: tile 128x256, K=128 =================
// Warp tile 64x64. Epilogue: accumulators -> smem (128x260 fp32), then each
// warp runs packed-key/redux top-8 over 16 rows, writing 8 candidates/row.
#define SC_LD 260
__global__ __launch_bounds__(256) void gemm2_topk(
    const __nv_bfloat16* __restrict__ Aq,    // [NT,256]
    const __nv_bfloat16* __restrict__ Keys,  // [2,256,128]
    unsigned* __restrict__ cand)             // [NT,16]
{
    extern __shared__ __align__(128) char dsm[];
    const unsigned sbase = smem_u32(dsm);

    const int tid = threadIdx.x, lane = tid & 31, wid = tid >> 5;
    const int m0 = blockIdx.x * 128;
    const int z  = blockIdx.y;

    const __nv_bfloat16* __restrict__ Ab = Aq + (size_t)m0 * (2 * D_KEY) + z * D_KEY;
    const __nv_bfloat16* __restrict__ Bb = Keys + (size_t)z * N_SUB * D_KEY;

    const int wm = (wid & 1) * 64;
    const int wn = (wid >> 1) * 64;

    const int rowA = wm + (lane & 15);
    const unsigned swzA = ((unsigned)rowA >> 1) & 3;
    const unsigned aBase = (unsigned)rowA * 64;
    const unsigned aSel = lane >> 4;
    const int rowB = wn + (lane & 7) + ((lane >> 4) << 3);
    const unsigned swzB = ((unsigned)rowB >> 1) & 3;
    const unsigned bBase = (unsigned)rowB * 64;
    const unsigned bSel = (lane >> 3) & 1;

    float acc[4][8][4];
    #pragma unroll
    for (int mt = 0; mt < 4; mt++)
        #pragma unroll
        for (int nt = 0; nt < 8; nt++)
            #pragma unroll
            for (int e = 0; e < 4; e++) acc[mt][nt][e] = 0.f;

    // stage: A 8KB @ +0, B 16KB @ +8192; stride 24576; 3 stages = 73728
    auto fill = [&](int kt, int st) {
        const unsigned base = sbase + st * 24576u;
        const int kb = kt * 32;
        #pragma unroll
        for (int u = 0; u < 2; u++) {        // A: 512 segs
            int idx = tid + u * 256;
            int r = idx >> 2, c = idx & 3;
            unsigned soff = (unsigned)r * 64 + (((unsigned)c ^ (((unsigned)r >> 1) & 3)) << 4);
            cpa16(base + soff, Ab + (size_t)r * (2 * D_KEY) + kb + c * 8);
        }
        #pragma unroll
        for (int u = 0; u < 4; u++) {        // B: 1024 segs
            int idx = tid + u * 256;
            int r = idx >> 2, c = idx & 3;
            unsigned soff = (unsigned)r * 64 + (((unsigned)c ^ (((unsigned)r >> 1) & 3)) << 4);
            cpa16(base + 8192u + soff, Bb + (size_t)r * D_KEY + kb + c * 8);
        }
    };

    const int KT = 4;   // K=128
    fill(0, 0); cpcommit();
    fill(1, 1); cpcommit();

    for (int kt = 0; kt < KT; kt++) {
        cpwait<1>();
        __syncthreads();
        int pf = kt + 2;
        if (pf < KT) fill(pf, pf % 3);
        cpcommit();

        const unsigned As = sbase + (kt % 3) * 24576u;
        const unsigned Bs = As + 8192u;
        #pragma unroll
        for (int kk = 0; kk < 2; kk++) {
            unsigned a[4][4];
            #pragma unroll
            for (int mt = 0; mt < 4; mt++)
                ldsm4(As + aBase + mt * 1024u + ((((unsigned)(kk * 2) + aSel) ^ swzA) << 4),
                      a[mt][0], a[mt][1], a[mt][2], a[mt][3]);
            unsigned b[8][2];
            #pragma unroll
            for (int g = 0; g < 4; g++) {
                unsigned r0, r1, r2, r3;
                ldsm4(Bs + bBase + g * 1024u + ((((unsigned)(kk * 2) + bSel) ^ swzB) << 4),
                      r0, r1, r2, r3);
                b[g * 2][0] = r0; b[g * 2][1] = r1;
                b[g * 2 + 1][0] = r2; b[g * 2 + 1][1] = r3;
            }
            #pragma unroll
            for (int mt = 0; mt < 4; mt++)
                #pragma unroll
                for (int nt = 0; nt < 8; nt++)
                    mma16816(acc[mt][nt], a[mt], b[nt]);
        }
        __syncthreads();
    }

    // ---- dump accumulators to smem score buffer [128][SC_LD] ----
    float* sc = (float*)dsm;
    const int gid = lane >> 2;
    const int tg  = (lane & 3) * 2;
    __syncthreads();   // pipeline smem dead; reuse
    #pragma unroll
    for (int mt = 0; mt < 4; mt++) {
        int r = wm + mt * 16 + gid;
        #pragma unroll
        for (int nt = 0; nt < 8; nt++) {
            int col = wn + nt * 8 + tg;
            *(float2*)&sc[(size_t)r * SC_LD + col]       = make_float2(acc[mt][nt][0], acc[mt][nt][1]);
            *(float2*)&sc[(size_t)(r + 8) * SC_LD + col] = make_float2(acc[mt][nt][2], acc[mt][nt][3]);
        }
    }
    __syncthreads();

    // ---- per-warp top-8 over 16 rows (cols s*32+lane: conflict-free) ----
    for (int j = 0; j < 16; j++) {
        const int r = wid * 16 + j;
        unsigned ks[8];
        #pragma unroll
        for (int s = 0; s < 8; s++) {
            float v = sc[(size_t)r * SC_LD + s * 32 + lane];
            ks[s] = (fmono(v) & 0xFFFFFF00u) | (255u - (unsigned)(s * 32 + lane));
        }
        unsigned my = 0u;
        #pragma unroll
        for (int it = 0; it < TOPK; it++) {
            unsigned loc = ks[0];
            #pragma unroll
            for (int s = 1; s < 8; s++) loc = max(loc, ks[s]);
            unsigned w = redux_max(loc);
            if (lane == it) my = w;
            #pragma unroll
            for (int s = 0; s < 8; s++) if (ks[s] == w) ks[s] = 0u;
        }
        if (lane < TOPK)
            cand[(size_t)(m0 + r) * 16 + z * 8 + lane] = my;
    }
}

// ================= combine: 64 cartesian candidates -> top-8 + softmax =================
__global__ __launch_bounds__(256) void combine_kernel(
    const unsigned* __restrict__ cand,
    float* __restrict__ wts, int* __restrict__ idxs, int NT)
{
    const unsigned FULL = 0xffffffffu;
    const int lane = threadIdx.x & 31;
    const int t = blockIdx.x * 8 + (threadIdx.x >> 5);
    if (t >= NT) return;
    const unsigned* c = cand + (size_t)t * 16;

    unsigned a0k = __ldg(c + (lane >> 3));
    unsigned a1k = __ldg(c + (lane >> 3) + 4);
    unsigned bk  = __ldg(c + 8 + (lane & 7));
    float bvf = funmono(bk & 0xFFFFFF00u);
    float c0 = funmono(a0k & 0xFFFFFF00u) + bvf;
    float c1 = funmono(a1k & 0xFFFFFF00u) + bvf;
    int ib  = 255 - (int)(bk & 255u);
    int idx0 = (255 - (int)(a0k & 255u)) * N_SUB + ib;
    int idx1 = (255 - (int)(a1k & 255u)) * N_SUB + ib;
    unsigned k0 = (fmono(c0) & ~63u) | (63u - (unsigned)lane);
    unsigned k1 = (fmono(c1) & ~63u) | (63u - (unsigned)(lane + 32));

    unsigned fkey = 0u; int fid = 0;
    #pragma unroll
    for (int it = 0; it < TOPK; it++) {
        unsigned loc = redux_max(max(k0, k1));
        unsigned pos = 63u - (loc & 63u);
        int src = (int)(pos & 31u);
        int widx = (pos < 32u) ? __shfl_sync(FULL, idx0, src)
                               : __shfl_sync(FULL, idx1, src);
        if (lane == it) { fkey = loc; fid = widx; }
        if (k0 == loc) k0 = 0u;
        if (k1 == loc) k1 = 0u;
    }

    float val = funmono(fkey & ~63u);
    float v0 = __shfl_sync(FULL, val, 0);
    float e = (lane < TOPK) ? expf(val - v0) : 0.f;
    float ssum = e;
    #pragma unroll
    for (int off = 4; off; off >>= 1) ssum += __shfl_xor_sync(FULL, ssum, off);
    if (lane < TOPK) {
        wts[(size_t)t * TOPK + lane]  = e / ssum;
        idxs[(size_t)t * TOPK + lane] = fid;
    }
}

// ================= gather + gate + residual (R6, proven) =================
__global__ __launch_bounds__(256) void gather_kernel(
    const float* __restrict__ x, const float* __restrict__ values,
    const float* __restrict__ gate_w, const float* __restrict__ gate_b,
    const float* __restrict__ wts, const int* __restrict__ idxs,
    float* __restrict__ out)
{
    const int t = blockIdx.x;
    const int tid = threadIdx.x;
    const int lane = tid & 31, wid = tid >> 5;

    const float4* xr = (const float4*)(x + (size_t)t * D_MODEL);
    const float4* gw = (const float4*)gate_w;

    float4 xv = xr[tid];
    float4 gv = gw[tid];
    float p = xv.x * gv.x + xv.y * gv.y + xv.z * gv.z + xv.w * gv.w;
    #pragma unroll
    for (int off = 16; off; off >>= 1) p += __shfl_down_sync(0xffffffffu, p, off);

    __shared__ float red[8];
    __shared__ float sw[TOPK];
    __shared__ int   sid[TOPK];
    __shared__ float sg;
    if (lane == 0) red[wid] = p;
    if (tid >= 32 && tid < 32 + TOPK) {
        sw[tid - 32]  = wts[(size_t)t * TOPK + (tid - 32)];
        sid[tid - 32] = idxs[(size_t)t * TOPK + (tid - 32)];
    }
    __syncthreads();
    if (tid == 0) {
        float s = red[0];
        #pragma unroll
        for (int w = 1; w < 8; w++) s += red[w];
        sg = 1.f / (1.f + expf(-(s + gate_b[0])));
    }
    __syncthreads();
    const float g = sg;

    float4 acc = make_float4(0.f, 0.f, 0.f, 0.f);
    #pragma unroll
    for (int k = 0; k < TOPK; k++) {
        const float4* vr = (const float4*)(values + (size_t)sid[k] * D_MODEL);
        float4 vv = __ldg(vr + tid);
        float w = sw[k];
        acc.x += w * vv.x; acc.y += w * vv.y; acc.z += w * vv.z; acc.w += w * vv.w;
    }
    float4 o;
    o.x = xv.x + g * acc.x;
    o.y = xv.y + g * acc.y;
    o.z = xv.z + g * acc.z;
    o.w = xv.w + g * acc.w;
    ((float4*)(out + (size_t)t * D_MODEL))[tid] = o;
}

// ================= launch =================
extern "C" void kernel_launch(void* const* d_in, const int* in_sizes, int n_in,
                              void* d_out, int out_size)
{
    const float* x      = (const float*)d_in[0];
    const float* keys_a = (const float*)d_in[1];
    const float* keys_b = (const float*)d_in[2];
    const float* values = (const float*)d_in[3];
    const float* Wq     = (const float*)d_in[4];
    const float* gate_w = (const float*)d_in[5];
    const float* gate_b = (const float*)d_in[6];
    float* out = (float*)d_out;

    const int NT = in_sizes[0] / D_MODEL;   // 8192

    __nv_bfloat16 *xb, *wqb, *kbb, *qb;
    unsigned* cbuf; float* wbuf; int* ibuf;
    cudaGetSymbolAddress((void**)&xb,   g_xb);
    cudaGetSymbolAddress((void**)&wqb,  g_wqb);
    cudaGetSymbolAddress((void**)&kbb,  g_kb);
    cudaGetSymbolAddress((void**)&qb,   g_qb);
    cudaGetSymbolAddress((void**)&cbuf, g_cand);
    cudaGetSymbolAddress((void**)&wbuf, g_wts);
    cudaGetSymbolAddress((void**)&ibuf, g_idx);

    // 0) convert inputs to bf16
    {
        int X4 = NT * D_MODEL / 4;
        int total = X4 + (2 * D_KEY * D_MODEL) / 4 + 2 * (N_SUB * D_KEY) / 4;
        convert_kernel<<<(total + 255) / 256, 256>>>(
            (const float4*)x, (const float4*)Wq, (const float4*)keys_a, (const float4*)keys_b,
            (uint2*)xb, (uint2*)wqb, (uint2*)kbb, X4);
    }
    // 1) q = x @ Wq^T -> bf16 [NT,256]
    {
        dim3 grid(NT / 128, (2 * D_KEY) / 128);
        hmma_gemm1<<<grid, 256>>>(xb, D_MODEL, wqb, D_MODEL, qb, 2 * D_KEY, D_MODEL);
    }
    // 2) scores + per-half top-8 fused (tile 128x256, grid.y = half)
    {
        const int dsm = 128 * SC_LD * 4;   // 133120 >= 3*24576 pipeline
        cudaFuncSetAttribute(gemm2_topk, cudaFuncAttributeMaxDynamicSharedMemorySize, dsm);
        dim3 grid(NT / 128, 2);
        gemm2_topk<<<grid, 256, dsm>>>(qb, kbb, cbuf);
    }
    // 3) cartesian combine + softmax
    combine_kernel<<<(NT + 7) / 8, 256>>>(cbuf, wbuf, ibuf, NT);
    // 4) gather + gate + residual
    gather_kernel<<<NT, 256>>>(x, values, gate_w, gate_b, wbuf, ibuf, out);
}